// round 7
// baseline (speedup 1.0000x reference)
#include <cuda_runtime.h>

#define NBLK    128
#define TPB     256
#define TSTEPS  128
#define BB      256
#define HH      256
#define INF     128
#define OUTF    128
#define G3H     768
#define M3B     768
#define AP      260      // sA row pitch (floats)
#define RBAND   48       // rows per band
#define CT      32       // gate-cols per CTA (actual cols = 3*CT = 96)
#define CLSZ    8        // CTAs per band

typedef unsigned long long ull;

// ---------------- device scratch ----------------
__device__ float g_gx[(size_t)TSTEPS * BB * G3H];   // x@Wx+bx, [t][b][3H]
__device__ float g_h0[M3B * HH];                    // ping-pong recurrent state
__device__ float g_h1[M3B * HH];
__device__ unsigned int g_bcnt[16 * 32];            // prologue band barrier
__device__ unsigned int g_bgen[16 * 32];
__device__ unsigned int g_flag[16 * 8 * 32];        // per-CTA step flags, 128B stride

// ---------------- helpers ----------------
__device__ __forceinline__ ull pack2(float v) {
    ull r; unsigned int u = __float_as_uint(v);
    asm("mov.b64 %0, {%1, %2};" : "=l"(r) : "r"(u), "r"(u));
    return r;
}
__device__ __forceinline__ void ffma2(ull& c, ull a, ull b) {
    asm("fma.rn.f32x2 %0, %1, %2, %0;" : "+l"(c) : "l"(a), "l"(b));
}
__device__ __forceinline__ float2 unpk(ull v) {
    float2 r; asm("mov.b64 {%0, %1}, %2;" : "=f"(r.x), "=f"(r.y) : "l"(v));
    return r;
}
union F4U { ull u[2]; float4 f; };

__device__ __forceinline__ float sigm(float x) {
    float e = __expf(-x);
    return __fdividef(1.0f, 1.0f + e);
}
__device__ __forceinline__ float tanh_fast(float x) {
    float ax = fabsf(x);
    float e  = __expf(-2.0f * ax);
    float t  = 1.0f - __fdividef(2.0f * e, 1.0f + e);
    return copysignf(t, x);
}
// L2-only async copy
__device__ __forceinline__ void cpa16(unsigned int saddr, const void* gptr) {
    asm volatile("cp.async.cg.shared.global [%0], [%1], 16;" :: "r"(saddr), "l"(gptr) : "memory");
}
__device__ __forceinline__ unsigned int ld_acq(const unsigned int* p) {
    unsigned int v;
    asm volatile("ld.acquire.gpu.global.b32 %0, [%1];" : "=r"(v) : "l"(p) : "memory");
    return v;
}
__device__ __forceinline__ void st_rel(unsigned int* p, unsigned int v) {
    asm volatile("st.release.gpu.global.b32 [%0], %1;" :: "l"(p), "r"(v) : "memory");
}

// full 8-participant band barrier (prologue only)
__device__ __forceinline__ void band_bar(int band) {
    __syncthreads();
    if (threadIdx.x == 0) {
        unsigned int* cnt = &g_bcnt[band * 32];
        volatile unsigned int* gen = (volatile unsigned int*)&g_bgen[band * 32];
        unsigned int g = *gen;
        __threadfence();
        if (atomicAdd(cnt, 1u) == CLSZ - 1) {
            *cnt = 0;
            __threadfence();
            *gen = g + 1;
        } else {
            while (*gen == g) { }
            __threadfence();
        }
    }
    __syncthreads();
}

// ---------------- phase 1: GX = X @ Wx + bx ----------------
__global__ void __launch_bounds__(TPB) gx_kernel(const float* __restrict__ x,
                                                 const float* __restrict__ Wx,
                                                 const float* __restrict__ bx) {
    __shared__ float sX[64 * 68];
    __shared__ float sW[64 * 64];
    const int tid = threadIdx.x;
    const int m0 = blockIdx.x * 64;
    const int n0 = blockIdx.y * 64;
    const int tyr = (tid >> 4) << 2;
    const int txc = (tid & 15) << 2;

    ull acc[4][2];
#pragma unroll
    for (int i = 0; i < 4; ++i) { acc[i][0] = 0ULL; acc[i][1] = 0ULL; }

    for (int k0 = 0; k0 < INF; k0 += 64) {
        __syncthreads();
#pragma unroll
        for (int i = tid; i < 64 * 64; i += TPB) {
            int rl = i >> 6, kk = i & 63;
            int m = m0 + rl;
            int tt = m >> 8, bb2 = m & 255;
            sX[kk * 68 + rl] = x[bb2 * (TSTEPS * INF) + tt * INF + k0 + kk];
        }
#pragma unroll
        for (int i = tid; i < 64 * 64; i += TPB) {
            int kk = i >> 6, n = i & 63;
            sW[kk * 64 + n] = Wx[(k0 + kk) * G3H + n0 + n];
        }
        __syncthreads();
#pragma unroll 8
        for (int kk = 0; kk < 64; ++kk) {
            float4 a4 = *(const float4*)(sX + kk * 68 + tyr);
            ulonglong2 bv = *(const ulonglong2*)(sW + kk * 64 + txc);
            ull a;
            a = pack2(a4.x); ffma2(acc[0][0], a, bv.x); ffma2(acc[0][1], a, bv.y);
            a = pack2(a4.y); ffma2(acc[1][0], a, bv.x); ffma2(acc[1][1], a, bv.y);
            a = pack2(a4.z); ffma2(acc[2][0], a, bv.x); ffma2(acc[2][1], a, bv.y);
            a = pack2(a4.w); ffma2(acc[3][0], a, bv.x); ffma2(acc[3][1], a, bv.y);
        }
    }
    float4 bx4 = *(const float4*)(bx + n0 + txc);
#pragma unroll
    for (int i = 0; i < 4; ++i) {
        F4U cv; cv.u[0] = acc[i][0]; cv.u[1] = acc[i][1];
        cv.f.x += bx4.x; cv.f.y += bx4.y; cv.f.z += bx4.z; cv.f.w += bx4.w;
        *(float4*)(g_gx + (size_t)(m0 + tyr + i) * G3H + n0 + txc) = cv.f;
    }
}

// GEMM inner step over one packed k-pair index kp
#define GBODY(kp) { \
    float2 a0 = *(const float2*)(saty + 2 * (kp)); \
    float2 a1 = *(const float2*)(saty + AP + 2 * (kp)); \
    float2 a2 = *(const float2*)(saty + 2 * AP + 2 * (kp)); \
    const float* wb = sWh + (kp) * 192 + tx4; \
    ulonglong2 wR = *(const ulonglong2*)(wb); \
    ulonglong2 wZ = *(const ulonglong2*)(wb + 64); \
    ulonglong2 wN = *(const ulonglong2*)(wb + 128); \
    ull a; \
    a = pack2(a0.x); ffma2(acc[0][0], a, wR.x); ffma2(acc[0][1], a, wZ.x); ffma2(acc[0][2], a, wN.x); \
    a = pack2(a1.x); ffma2(acc[1][0], a, wR.x); ffma2(acc[1][1], a, wZ.x); ffma2(acc[1][2], a, wN.x); \
    a = pack2(a2.x); ffma2(acc[2][0], a, wR.x); ffma2(acc[2][1], a, wZ.x); ffma2(acc[2][2], a, wN.x); \
    a = pack2(a0.y); ffma2(acc[0][0], a, wR.y); ffma2(acc[0][1], a, wZ.y); ffma2(acc[0][2], a, wN.y); \
    a = pack2(a1.y); ffma2(acc[1][0], a, wR.y); ffma2(acc[1][1], a, wZ.y); ffma2(acc[1][2], a, wN.y); \
    a = pack2(a2.y); ffma2(acc[2][0], a, wR.y); ffma2(acc[2][1], a, wZ.y); ffma2(acc[2][2], a, wN.y); \
}

// GEMM over 16 kp of slab j
#define GEMM_SLAB(j) { \
    _Pragma("unroll 4") \
    for (int kp = (j) * 16; kp < (j) * 16 + 16; ++kp) GBODY(kp); \
}

// async-load slab j of hbuf into sA (48 rows x 32 cols = 384 x 16B)
#define LOAD_SLAB(j, hp) { \
    for (int c = tid; c < 384; c += TPB) { \
        int row = c >> 3, f = (c & 7) << 2; \
        cpa16(sA_b + (unsigned)((row * AP + (j) * CT + f) << 2), \
              (hp) + (rm0 + row) * HH + (j) * CT + f); \
    } \
    asm volatile("cp.async.commit_group;" ::: "memory"); \
}

// ---------------- phase 2: persistent scan, flag-pipelined slabs ----------------
__global__ void __launch_bounds__(TPB, 1)
cru_persistent(const float* __restrict__ hid,
               const float* __restrict__ Wh,
               const float* __restrict__ bh) {
    extern __shared__ float smem[];
    float* sWh = smem;                       // packed Wh: [kp][gate][tx][4]
    float* sA  = smem + 24576;               // [48][AP]
    float* sGx = smem + 24576 + RBAND * AP;  // [2][48][96]

    const int tid = threadIdx.x;
    const int bid = blockIdx.x;
    const int band  = bid >> 3;
    const int ctile = bid & 7;
    const int rm0 = band * RBAND;
    const int k0  = ctile * CT;
    const int ty = tid >> 4, tx = tid & 15;
    const int ty3 = ty * 3, tx2 = tx * 2, tx4 = tx * 4;
    const unsigned int sA_b  = (unsigned int)__cvta_generic_to_shared(sA);
    const unsigned int sGx_b = (unsigned int)__cvta_generic_to_shared(sGx);
    unsigned int* myflag = &g_flag[(band * 8 + ctile) * 32];
    const unsigned int E = *myflag;          // epoch from prior launch (own flag, race-free)

    // packed Wh slice
    for (int i = tid; i < 24576; i += TPB) {
        int kp = i / 192, r = i - kp * 192;
        int g = r >> 6, q = r & 63;
        int txi = q >> 2, j = q & 3;
        int kk = 2 * kp + (j >> 1);
        int c  = txi * 2 + (j & 1);
        sWh[i] = Wh[kk * G3H + g * HH + k0 + c];
    }
    // init own slab of h_0: rows rm0..+48, cols k0..+32
    for (int c = tid; c < 768; c += TPB) {   // 768 float2
        int row = c >> 4, f = (c & 15) << 1;
        *(float2*)&g_h0[(rm0 + row) * HH + k0 + f] =
            *(const float2*)&hid[(rm0 + row) * HH + k0 + f];
    }
    band_bar(band);   // all slabs of h_0 written

    // prologue: full sA fill (h_0) + gx[0] prefetch
#pragma unroll
    for (int j = 0; j < 12; ++j) {
        int i = tid + TPB * j;
        int row = i >> 6, c16 = i & 63;
        cpa16(sA_b + (unsigned)((row * AP + (c16 << 2)) << 2),
              g_h0 + (rm0 + row) * HH + (c16 << 2));
    }
    for (int c = tid; c < 1152; c += TPB) {
        int row = c / 24;
        int q = c - row * 24;
        int seg = q >> 3;
        int f0 = (q & 7) << 2;
        int b = (rm0 + row) & 255;
        cpa16(sGx_b + (unsigned)((row * 96 + seg * 32 + f0) << 2),
              g_gx + (size_t)b * G3H + seg * HH + k0 + f0);
    }
    asm volatile("cp.async.commit_group;" ::: "memory");
    asm volatile("cp.async.wait_group 0;" ::: "memory");
    __syncthreads();

    const float bhr0 = bh[k0 + tx2],          bhr1 = bh[k0 + tx2 + 1];
    const float bhz0 = bh[HH + k0 + tx2],     bhz1 = bh[HH + k0 + tx2 + 1];
    const float bhn0 = bh[2 * HH + k0 + tx2], bhn1 = bh[2 * HH + k0 + tx2 + 1];

    for (int t = 0; t < TSTEPS; ++t) {
        const float* hin  = (t & 1) ? g_h1 : g_h0;   // h_t
        float*       hout = (t & 1) ? g_h0 : g_h1;   // h_{t+1}
        const int buf = t & 1;
        const unsigned int want = E + (unsigned)t;   // flag value meaning "h_t slab ready"

        // ---- hold: own h_t cols (each thread reads what it wrote; smem) ----
        float2 hold[3];
#pragma unroll
        for (int r = 0; r < 3; ++r)
            hold[r] = *(const float2*)(sA + (ty3 + r) * AP + k0 + tx2);

        // ---- group G: gx[t+1] prefetch ----
        if (t + 1 < TSTEPS) {
            const float* gxb = g_gx + (size_t)(t + 1) * BB * G3H;
            for (int c = tid; c < 1152; c += TPB) {
                int row = c / 24;
                int q = c - row * 24;
                int seg = q >> 3;
                int f0 = (q & 7) << 2;
                int b = (rm0 + row) & 255;
                cpa16(sGx_b + (unsigned)(((buf ^ 1) * 4608 + row * 96 + seg * 32 + f0) << 2),
                      gxb + (size_t)b * G3H + seg * HH + k0 + f0);
            }
        }
        asm volatile("cp.async.commit_group;" ::: "memory");

        ull acc[3][3];
#pragma unroll
        for (int r = 0; r < 3; ++r) { acc[r][0] = 0ULL; acc[r][1] = 0ULL; acc[r][2] = 0ULL; }
        const float* saty = sA + ty3 * AP;

        // ---- pipeline: wait flag j -> load slab j; GEMM previous slab ----
        {
            int j1 = (ctile + 1) & 7;
            if (tid == 0) {
                const unsigned int* f = &g_flag[(band * 8 + j1) * 32];
                while ((int)(ld_acq(f) - want) < 0) { }
            }
            __syncthreads();
            LOAD_SLAB(j1, hin);
        }
        GEMM_SLAB(ctile);                        // own slab: already in sA

#pragma unroll 1
        for (int d = 1; d <= 6; ++d) {
            int jn = (ctile + d + 1) & 7;
            int jd = (ctile + d) & 7;
            if (tid == 0) {
                const unsigned int* f = &g_flag[(band * 8 + jn) * 32];
                while ((int)(ld_acq(f) - want) < 0) { }
            }
            __syncthreads();
            LOAD_SLAB(jn, hin);
            asm volatile("cp.async.wait_group 1;" ::: "memory");   // slab jd arrived
            __syncthreads();
            GEMM_SLAB(jd);
        }
        asm volatile("cp.async.wait_group 0;" ::: "memory");       // last slab + gx
        __syncthreads();
        GEMM_SLAB((ctile + 7) & 7);

        // ---- gate update in registers ----
        float2 hnew[3];
#pragma unroll
        for (int r = 0; r < 3; ++r) {
            float2 Gr = unpk(acc[r][0]);
            float2 Gz = unpk(acc[r][1]);
            float2 Gn = unpk(acc[r][2]);
            const float* gp = sGx + buf * 4608 + (ty3 + r) * 96 + tx2;
            float2 gxr = *(const float2*)(gp);
            float2 gxz = *(const float2*)(gp + 32);
            float2 gxn = *(const float2*)(gp + 64);
            float R0 = sigm(gxr.x + Gr.x + bhr0);
            float R1 = sigm(gxr.y + Gr.y + bhr1);
            float Z0 = sigm(gxz.x + Gz.x + bhz0);
            float Z1 = sigm(gxz.y + Gz.y + bhz1);
            float N0 = tanh_fast(gxn.x + R0 * (Gn.x + bhn0));
            float N1 = tanh_fast(gxn.y + R1 * (Gn.y + bhn1));
            hnew[r].x = N0 + Z0 * (hold[r].x - N0);
            hnew[r].y = N1 + Z1 * (hold[r].y - N1);
        }

        // ---- store h_{t+1}: own cols to sA + global, then release flag ----
#pragma unroll
        for (int r = 0; r < 3; ++r) {
            *(float2*)(sA + (ty3 + r) * AP + k0 + tx2) = hnew[r];
            __stcg((float2*)(hout + (rm0 + ty3 + r) * HH + k0 + tx2), hnew[r]);
        }
        __syncthreads();
        if (tid == 0) {
            __threadfence();
            st_rel(myflag, E + (unsigned)(t + 1));
        }
    }
}

// ---------------- phase 3: output head (h_128 in g_h0) ----------------
__global__ void __launch_bounds__(TPB) head_kernel(const float* __restrict__ Wf,
                                                   const float* __restrict__ bf,
                                                   float* __restrict__ out) {
    const int bid = blockIdx.x;
    const int tid = threadIdx.x;
    if (bid < 128) {
        __shared__ float s[2][256];
        int rb0 = bid << 1;
#pragma unroll
        for (int j = 0; j < 2; ++j)
            s[j][tid] = __ldcg(&g_h0[(rb0 + j) * HH + tid])
                      + __ldcg(&g_h0[(256 + rb0 + j) * HH + tid])
                      + __ldcg(&g_h0[(512 + rb0 + j) * HH + tid]);
        __syncthreads();
        int r = tid >> 7, o = tid & 127;
        float acc = bf[o];
        const float* sr = s[r];
#pragma unroll 8
        for (int k = 0; k < HH; ++k)
            acc = fmaf(sr[k], __ldg(Wf + k * OUTF + o), acc);
        out[(rb0 + r) * OUTF + o] = (acc > 0.0f) ? acc : expm1f(acc);
    } else {
        int c = bid - 128;
        float acc = 0.0f;
#pragma unroll 8
        for (int b2 = 0; b2 < BB; ++b2)
            acc += __ldcg(&g_h0[(c * 256 + b2) * HH + tid]);
        out[BB * OUTF + c * HH + tid] = acc * (1.0f / 256.0f);
    }
}

// ---------------- launch ----------------
extern "C" void kernel_launch(void* const* d_in, const int* in_sizes, int n_in,
                              void* d_out, int out_size) {
    const float* x   = (const float*)d_in[0];
    const float* hid = (const float*)d_in[1];
    const float* Wx  = (const float*)d_in[2];
    const float* bx  = (const float*)d_in[3];
    const float* Wh  = (const float*)d_in[4];
    const float* bh  = (const float*)d_in[5];
    const float* Wf  = (const float*)d_in[6];
    const float* bf  = (const float*)d_in[7];
    float* out = (float*)d_out;

    const int smem_p = (24576 + RBAND * AP + 2 * RBAND * 96) * (int)sizeof(float); // 185088
    cudaFuncSetAttribute(cru_persistent, cudaFuncAttributeMaxDynamicSharedMemorySize, smem_p);

    gx_kernel<<<dim3(512, 12), TPB>>>(x, Wx, bx);
    cru_persistent<<<NBLK, TPB, smem_p>>>(hid, Wh, bh);
    head_kernel<<<131, TPB>>>(Wf, bf, out);
}

// round 8
// speedup vs baseline: 1.2506x; 1.2506x over previous
#include <cuda_runtime.h>

#define NBLK    128
#define TPB     256
#define TSTEPS  128
#define BB      256
#define HH      256
#define INF     128
#define OUTF    128
#define G3H     768
#define M3B     768
#define AP      260      // sA row pitch (floats)
#define RBAND   48       // rows per band
#define CT      32       // gate-cols per CTA (actual cols = 3*CT = 96)
#define CLSZ    8        // CTAs per band

typedef unsigned long long ull;

// ---------------- device scratch ----------------
__device__ float g_gx[(size_t)TSTEPS * BB * G3H];   // x@Wx+bx, [t][b][3H]
__device__ float g_h0[M3B * HH];                    // ping-pong recurrent state
__device__ float g_h1[M3B * HH];
__device__ unsigned int g_bcnt[16 * 32];            // prologue band barrier
__device__ unsigned int g_bgen[16 * 32];
__device__ unsigned int g_flag[16 * 8 * 32];        // per-CTA step flags, 128B stride

// ---------------- helpers ----------------
__device__ __forceinline__ ull pack2(float v) {
    ull r; unsigned int u = __float_as_uint(v);
    asm("mov.b64 %0, {%1, %2};" : "=l"(r) : "r"(u), "r"(u));
    return r;
}
__device__ __forceinline__ void ffma2(ull& c, ull a, ull b) {
    asm("fma.rn.f32x2 %0, %1, %2, %0;" : "+l"(c) : "l"(a), "l"(b));
}
__device__ __forceinline__ float2 unpk(ull v) {
    float2 r; asm("mov.b64 {%0, %1}, %2;" : "=f"(r.x), "=f"(r.y) : "l"(v));
    return r;
}
union F4U { ull u[2]; float4 f; };

__device__ __forceinline__ float sigm(float x) {
    float e = __expf(-x);
    return __fdividef(1.0f, 1.0f + e);
}
__device__ __forceinline__ float tanh_fast(float x) {
    float ax = fabsf(x);
    float e  = __expf(-2.0f * ax);
    float t  = 1.0f - __fdividef(2.0f * e, 1.0f + e);
    return copysignf(t, x);
}
// L2-only async copy
__device__ __forceinline__ void cpa16(unsigned int saddr, const void* gptr) {
    asm volatile("cp.async.cg.shared.global [%0], [%1], 16;" :: "r"(saddr), "l"(gptr) : "memory");
}
__device__ __forceinline__ unsigned int ld_acq(const unsigned int* p) {
    unsigned int v;
    asm volatile("ld.acquire.gpu.global.b32 %0, [%1];" : "=r"(v) : "l"(p) : "memory");
    return v;
}
__device__ __forceinline__ void st_rel(unsigned int* p, unsigned int v) {
    asm volatile("st.release.gpu.global.b32 [%0], %1;" :: "l"(p), "r"(v) : "memory");
}

// full 8-participant band barrier (prologue only)
__device__ __forceinline__ void band_bar(int band) {
    __syncthreads();
    if (threadIdx.x == 0) {
        unsigned int* cnt = &g_bcnt[band * 32];
        volatile unsigned int* gen = (volatile unsigned int*)&g_bgen[band * 32];
        unsigned int g = *gen;
        __threadfence();
        if (atomicAdd(cnt, 1u) == CLSZ - 1) {
            *cnt = 0;
            __threadfence();
            *gen = g + 1;
        } else {
            while (*gen == g) { }
            __threadfence();
        }
    }
    __syncthreads();
}

// ---------------- phase 1: GX = X @ Wx + bx ----------------
__global__ void __launch_bounds__(TPB) gx_kernel(const float* __restrict__ x,
                                                 const float* __restrict__ Wx,
                                                 const float* __restrict__ bx) {
    __shared__ float sX[64 * 68];
    __shared__ float sW[64 * 64];
    const int tid = threadIdx.x;
    const int m0 = blockIdx.x * 64;
    const int n0 = blockIdx.y * 64;
    const int tyr = (tid >> 4) << 2;
    const int txc = (tid & 15) << 2;

    ull acc[4][2];
#pragma unroll
    for (int i = 0; i < 4; ++i) { acc[i][0] = 0ULL; acc[i][1] = 0ULL; }

    for (int k0 = 0; k0 < INF; k0 += 64) {
        __syncthreads();
#pragma unroll
        for (int i = tid; i < 64 * 64; i += TPB) {
            int rl = i >> 6, kk = i & 63;
            int m = m0 + rl;
            int tt = m >> 8, bb2 = m & 255;
            sX[kk * 68 + rl] = x[bb2 * (TSTEPS * INF) + tt * INF + k0 + kk];
        }
#pragma unroll
        for (int i = tid; i < 64 * 64; i += TPB) {
            int kk = i >> 6, n = i & 63;
            sW[kk * 64 + n] = Wx[(k0 + kk) * G3H + n0 + n];
        }
        __syncthreads();
#pragma unroll 8
        for (int kk = 0; kk < 64; ++kk) {
            float4 a4 = *(const float4*)(sX + kk * 68 + tyr);
            ulonglong2 bv = *(const ulonglong2*)(sW + kk * 64 + txc);
            ull a;
            a = pack2(a4.x); ffma2(acc[0][0], a, bv.x); ffma2(acc[0][1], a, bv.y);
            a = pack2(a4.y); ffma2(acc[1][0], a, bv.x); ffma2(acc[1][1], a, bv.y);
            a = pack2(a4.z); ffma2(acc[2][0], a, bv.x); ffma2(acc[2][1], a, bv.y);
            a = pack2(a4.w); ffma2(acc[3][0], a, bv.x); ffma2(acc[3][1], a, bv.y);
        }
    }
    float4 bx4 = *(const float4*)(bx + n0 + txc);
#pragma unroll
    for (int i = 0; i < 4; ++i) {
        F4U cv; cv.u[0] = acc[i][0]; cv.u[1] = acc[i][1];
        cv.f.x += bx4.x; cv.f.y += bx4.y; cv.f.z += bx4.z; cv.f.w += bx4.w;
        *(float4*)(g_gx + (size_t)(m0 + tyr + i) * G3H + n0 + txc) = cv.f;
    }
}

// GEMM inner step over one packed k-pair index kp
#define GBODY(kp) { \
    float2 a0 = *(const float2*)(saty + 2 * (kp)); \
    float2 a1 = *(const float2*)(saty + AP + 2 * (kp)); \
    float2 a2 = *(const float2*)(saty + 2 * AP + 2 * (kp)); \
    const float* wb = sWh + (kp) * 192 + tx4; \
    ulonglong2 wR = *(const ulonglong2*)(wb); \
    ulonglong2 wZ = *(const ulonglong2*)(wb + 64); \
    ulonglong2 wN = *(const ulonglong2*)(wb + 128); \
    ull a; \
    a = pack2(a0.x); ffma2(acc[0][0], a, wR.x); ffma2(acc[0][1], a, wZ.x); ffma2(acc[0][2], a, wN.x); \
    a = pack2(a1.x); ffma2(acc[1][0], a, wR.x); ffma2(acc[1][1], a, wZ.x); ffma2(acc[1][2], a, wN.x); \
    a = pack2(a2.x); ffma2(acc[2][0], a, wR.x); ffma2(acc[2][1], a, wZ.x); ffma2(acc[2][2], a, wN.x); \
    a = pack2(a0.y); ffma2(acc[0][0], a, wR.y); ffma2(acc[0][1], a, wZ.y); ffma2(acc[0][2], a, wN.y); \
    a = pack2(a1.y); ffma2(acc[1][0], a, wR.y); ffma2(acc[1][1], a, wZ.y); ffma2(acc[1][2], a, wN.y); \
    a = pack2(a2.y); ffma2(acc[2][0], a, wR.y); ffma2(acc[2][1], a, wZ.y); ffma2(acc[2][2], a, wN.y); \
}

// ---------------- phase 2: persistent scan, 16 independent bands x 8 CTAs ----------------
__global__ void __launch_bounds__(TPB, 1)
cru_persistent(const float* __restrict__ hid,
               const float* __restrict__ Wh,
               const float* __restrict__ bh) {
    extern __shared__ float smem[];
    float* sWh = smem;                       // packed Wh: [kp][gate][tx][4]
    float* sA  = smem + 24576;               // [48][AP]
    float* sGx = smem + 24576 + RBAND * AP;  // [2][48][96]

    const int tid = threadIdx.x;
    const int bid = blockIdx.x;
    const int band  = bid >> 3;
    const int ctile = bid & 7;
    const int rm0 = band * RBAND;
    const int k0  = ctile * CT;
    const int K0_2 = ctile * 16;             // own kp range start
    const int cbase = ctile * 8;             // own 16B-chunk-col base
    const int ty = tid >> 4, tx = tid & 15;
    const int ty3 = ty * 3, tx2 = tx * 2, tx4 = tx * 4;
    const unsigned int sA_b  = (unsigned int)__cvta_generic_to_shared(sA);
    const unsigned int sGx_b = (unsigned int)__cvta_generic_to_shared(sGx);
    unsigned int* myflag = &g_flag[(band * 8 + ctile) * 32];
    const unsigned int E = *myflag;          // epoch (own flag; monotonic, race-free)

    // packed Wh slice
    for (int i = tid; i < 24576; i += TPB) {
        int kp = i / 192, r = i - kp * 192;
        int g = r >> 6, q = r & 63;
        int txi = q >> 2, j = q & 3;
        int kk = 2 * kp + (j >> 1);
        int c  = txi * 2 + (j & 1);
        sWh[i] = Wh[kk * G3H + g * HH + k0 + c];
    }
    // init own slab of h_0
    for (int c = tid; c < 768; c += TPB) {   // 768 float2
        int row = c >> 4, f = (c & 15) << 1;
        *(float2*)&g_h0[(rm0 + row) * HH + k0 + f] =
            *(const float2*)&hid[(rm0 + row) * HH + k0 + f];
    }
    band_bar(band);   // all slabs of h_0 written

    // prologue: full sA fill (h_0) + gx[0] prefetch
#pragma unroll
    for (int j = 0; j < 12; ++j) {
        int i = tid + TPB * j;
        int row = i >> 6, c16 = i & 63;
        cpa16(sA_b + (unsigned)((row * AP + (c16 << 2)) << 2),
              g_h0 + (rm0 + row) * HH + (c16 << 2));
    }
    for (int c = tid; c < 1152; c += TPB) {
        int row = c / 24;
        int q = c - row * 24;
        int seg = q >> 3;
        int f0 = (q & 7) << 2;
        int b = (rm0 + row) & 255;
        cpa16(sGx_b + (unsigned)((row * 96 + seg * 32 + f0) << 2),
              g_gx + (size_t)b * G3H + seg * HH + k0 + f0);
    }
    asm volatile("cp.async.commit_group;" ::: "memory");
    asm volatile("cp.async.wait_group 0;" ::: "memory");
    __syncthreads();

    const float bhr0 = bh[k0 + tx2],          bhr1 = bh[k0 + tx2 + 1];
    const float bhz0 = bh[HH + k0 + tx2],     bhz1 = bh[HH + k0 + tx2 + 1];
    const float bhn0 = bh[2 * HH + k0 + tx2], bhn1 = bh[2 * HH + k0 + tx2 + 1];

    // hold: own h_0 values (carried in registers across steps)
    float2 hold[3];
#pragma unroll
    for (int r = 0; r < 3; ++r)
        hold[r] = *(const float2*)(sA + (ty3 + r) * AP + k0 + tx2);

    for (int t = 0; t < TSTEPS; ++t) {
        const float* hin  = (t & 1) ? g_h1 : g_h0;   // h_t
        float*       hout = (t & 1) ? g_h0 : g_h1;   // h_{t+1}
        const int buf = t & 1;
        const unsigned int want = E + (unsigned)t;   // "h_t slab ready"

        // ---- group G: gx[t+1] prefetch ----
        if (t + 1 < TSTEPS) {
            const float* gxb = g_gx + (size_t)(t + 1) * BB * G3H;
            for (int c = tid; c < 1152; c += TPB) {
                int row = c / 24;
                int q = c - row * 24;
                int seg = q >> 3;
                int f0 = (q & 7) << 2;
                int b = (rm0 + row) & 255;
                cpa16(sGx_b + (unsigned)(((buf ^ 1) * 4608 + row * 96 + seg * 32 + f0) << 2),
                      gxb + (size_t)b * G3H + seg * HH + k0 + f0);
            }
        }
        asm volatile("cp.async.commit_group;" ::: "memory");

        // ---- partial GEMM over own slab (local, overlaps peers' progress) ----
        ull acc[3][3];
#pragma unroll
        for (int r = 0; r < 3; ++r) { acc[r][0] = 0ULL; acc[r][1] = 0ULL; acc[r][2] = 0ULL; }
        const float* saty = sA + ty3 * AP;
#pragma unroll 8
        for (int i = 0; i < 16; ++i) { int kp = K0_2 + i; GBODY(kp); }

        // ---- parallel flag wait: lane j polls CTA j's flag ----
        if (tid < 32) {
            bool done = (tid >= 8);
            const unsigned int* f = &g_flag[(band * 8 + (tid & 7)) * 32];
            do {
                if (!done) done = ((int)(ld_acq(f) - want) >= 0);
            } while (!__all_sync(0xffffffffu, done));
        }
        __syncthreads();

        // ---- refill chunk A: 32 chunk-cols after own slab (circular) ----
        for (int c = tid; c < 1536; c += TPB) {
            int row = c >> 5, q = c & 31;
            int f = (cbase + 8 + q) & 63;
            cpa16(sA_b + (unsigned)((row * AP + (f << 2)) << 2),
                  hin + (rm0 + row) * HH + (f << 2));
        }
        asm volatile("cp.async.commit_group;" ::: "memory");

        // ---- refill chunk B: remaining 24 chunk-cols ----
        for (int c = tid; c < 1152; c += TPB) {
            int row = c / 24;
            int q = c - row * 24;
            int f = (cbase + 40 + q) & 63;
            cpa16(sA_b + (unsigned)((row * AP + (f << 2)) << 2),
                  hin + (rm0 + row) * HH + (f << 2));
        }
        asm volatile("cp.async.commit_group;" ::: "memory");

        // ---- wait chunk A (also drains gx group G), GEMM 64 kp ----
        asm volatile("cp.async.wait_group 1;" ::: "memory");
        __syncthreads();
#pragma unroll 4
        for (int i = 16; i < 80; ++i) { int kp = (K0_2 + i) & 127; GBODY(kp); }

        // ---- wait chunk B, GEMM 48 kp ----
        asm volatile("cp.async.wait_group 0;" ::: "memory");
        __syncthreads();
#pragma unroll 4
        for (int i = 80; i < 128; ++i) { int kp = (K0_2 + i) & 127; GBODY(kp); }

        // ---- gate update in registers ----
        float2 hnew[3];
#pragma unroll
        for (int r = 0; r < 3; ++r) {
            float2 Gr = unpk(acc[r][0]);
            float2 Gz = unpk(acc[r][1]);
            float2 Gn = unpk(acc[r][2]);
            const float* gp = sGx + buf * 4608 + (ty3 + r) * 96 + tx2;
            float2 gxr = *(const float2*)(gp);
            float2 gxz = *(const float2*)(gp + 32);
            float2 gxn = *(const float2*)(gp + 64);
            float R0 = sigm(gxr.x + Gr.x + bhr0);
            float R1 = sigm(gxr.y + Gr.y + bhr1);
            float Z0 = sigm(gxz.x + Gz.x + bhz0);
            float Z1 = sigm(gxz.y + Gz.y + bhz1);
            float N0 = tanh_fast(gxn.x + R0 * (Gn.x + bhn0));
            float N1 = tanh_fast(gxn.y + R1 * (Gn.y + bhn1));
            hnew[r].x = N0 + Z0 * (hold[r].x - N0);
            hnew[r].y = N1 + Z1 * (hold[r].y - N1);
            hold[r] = hnew[r];
        }

        // ---- store h_{t+1}: own cols into sA + global, then release flag ----
#pragma unroll
        for (int r = 0; r < 3; ++r) {
            *(float2*)(sA + (ty3 + r) * AP + k0 + tx2) = hnew[r];
            __stcg((float2*)(hout + (rm0 + ty3 + r) * HH + k0 + tx2), hnew[r]);
        }
        __syncthreads();
        if (tid == 0) {
            __threadfence();
            st_rel(myflag, E + (unsigned)(t + 1));
        }
    }
}

// ---------------- phase 3: output head (h_128 in g_h0) ----------------
__global__ void __launch_bounds__(TPB) head_kernel(const float* __restrict__ Wf,
                                                   const float* __restrict__ bf,
                                                   float* __restrict__ out) {
    const int bid = blockIdx.x;
    const int tid = threadIdx.x;
    if (bid < 128) {
        __shared__ float s[2][256];
        int rb0 = bid << 1;
#pragma unroll
        for (int j = 0; j < 2; ++j)
            s[j][tid] = __ldcg(&g_h0[(rb0 + j) * HH + tid])
                      + __ldcg(&g_h0[(256 + rb0 + j) * HH + tid])
                      + __ldcg(&g_h0[(512 + rb0 + j) * HH + tid]);
        __syncthreads();
        int r = tid >> 7, o = tid & 127;
        float acc = bf[o];
        const float* sr = s[r];
#pragma unroll 8
        for (int k = 0; k < HH; ++k)
            acc = fmaf(sr[k], __ldg(Wf + k * OUTF + o), acc);
        out[(rb0 + r) * OUTF + o] = (acc > 0.0f) ? acc : expm1f(acc);
    } else {
        int c = bid - 128;
        float acc = 0.0f;
#pragma unroll 8
        for (int b2 = 0; b2 < BB; ++b2)
            acc += __ldcg(&g_h0[(c * 256 + b2) * HH + tid]);
        out[BB * OUTF + c * HH + tid] = acc * (1.0f / 256.0f);
    }
}

// ---------------- launch ----------------
extern "C" void kernel_launch(void* const* d_in, const int* in_sizes, int n_in,
                              void* d_out, int out_size) {
    const float* x   = (const float*)d_in[0];
    const float* hid = (const float*)d_in[1];
    const float* Wx  = (const float*)d_in[2];
    const float* bx  = (const float*)d_in[3];
    const float* Wh  = (const float*)d_in[4];
    const float* bh  = (const float*)d_in[5];
    const float* Wf  = (const float*)d_in[6];
    const float* bf  = (const float*)d_in[7];
    float* out = (float*)d_out;

    const int smem_p = (24576 + RBAND * AP + 2 * RBAND * 96) * (int)sizeof(float); // 185088
    cudaFuncSetAttribute(cru_persistent, cudaFuncAttributeMaxDynamicSharedMemorySize, smem_p);

    gx_kernel<<<dim3(512, 12), TPB>>>(x, Wx, bx);
    cru_persistent<<<NBLK, TPB, smem_p>>>(hid, Wh, bh);
    head_kernel<<<131, TPB>>>(Wf, bf, out);
}